// round 15
// baseline (speedup 1.0000x reference)
#include <cuda_runtime.h>
#include <cuda_fp16.h>
#include <cstdint>

// ---------------------------------------------------------------------------
// out = concat( relu(A@relu(A@F)), A@(A@G) ), A:[8192,8192] f32, F,G:[8192,64]
// Per layer: fused GEMM C[8192,128] = A @ Bt^T, relu on cols [0,64).
// fp16 mma.m16n8k16; 4 producer + 4 consumer warps (R12 chassis).
// R15: layer-1 consumers side-write their packed fp16 A fragments to g_a16
// (fragment-ordered); layer-2 streams A16 via cp.async (4KB/stage vs 16KB)
// and loads fragments with 4x LDS.128 (no cvt). Smem traffic -25% in layer 2.
// ---------------------------------------------------------------------------

#define NN      8192
#define NB      128
#define MT      64              // M rows per CTA -> 128 CTAs
#define KT      32              // K per stage
#define STAGES  8
#define KIT     (NN / KT)       // 256
#define A_PITCH 160             // bytes per A smem row (fp32 k32 + pad)
#define B_PITCH 64              // bytes per B smem row (fp16 k32)
#define A_STG_B (64 * A_PITCH)  // 10240
#define B_STG_B (128 * B_PITCH) // 8192
#define STG_B   (A_STG_B + B_STG_B)        // 18432
#define SMEM_BYTES (STAGES * STG_B)        // 147456
#define STG_PITCH 136           // staging bytes per col (64 rows fp16 + pad)

__device__ __half g_bth1[NB * NN];   // layer-1 B, fp16 chunk-permuted
__device__ __half g_bth2[NB * NN];   // layer-1 out (x2^6) = layer-2 B
// A16 fragments: [block(128)][stage(256)][wm(2)][g(4)][lane(32)] x 16B = 128MB
__device__ uint4  g_a16[(size_t)128 * KIT * 256];

// chunk permutation within each k32 block (2-element chunks):
// chunk j -> position (j%4)*4 + j/4
__device__ __forceinline__ int kperm2(int k) {
    int j = (k >> 1) & 15;
    int p = ((j & 3) << 2) | (j >> 2);
    return (k & ~31) | (p << 1) | (k & 1);
}

__device__ __forceinline__ uint32_t smem_u32(const void* p) {
    uint32_t a;
    asm("{ .reg .u64 t; cvta.to.shared.u64 t, %1; cvt.u32.u64 %0, t; }"
        : "=r"(a) : "l"(p));
    return a;
}

// pack two fp32 -> fp16x2 (lo = first arg)
__device__ __forceinline__ uint32_t pack_h2(float lo, float hi) {
    uint32_t d;
    asm("cvt.rn.f16x2.f32 %0, %1, %2;" : "=r"(d) : "f"(hi), "f"(lo));
    return d;
}

#define CP_ASYNC16(dst, src) \
    asm volatile("cp.async.cg.shared.global [%0], [%1], 16;" \
                 :: "r"(dst), "l"(src) : "memory")

#define MBAR_INIT(addr, cnt) \
    asm volatile("mbarrier.init.shared.b64 [%0], %1;" :: "r"(addr), "r"(cnt) : "memory")
#define MBAR_ARRIVE(addr) \
    asm volatile("mbarrier.arrive.shared.b64 _, [%0];" :: "r"(addr) : "memory")
#define CP_ASYNC_MBAR_ARRIVE(addr) \
    asm volatile("cp.async.mbarrier.arrive.noinc.shared::cta.b64 [%0];" \
                 :: "r"(addr) : "memory")

#define MBAR_WAIT(addr, parity) do {                                          \
    uint32_t _mb = (addr); uint32_t _ph = (parity); uint32_t _done;           \
    asm volatile("{\n\t.reg .pred p;\n\t"                                     \
        "mbarrier.try_wait.parity.acquire.cta.shared::cta.b64 p, [%1], %2;\n\t"\
        "selp.b32 %0, 1, 0, p;\n\t}"                                          \
        : "=r"(_done) : "r"(_mb), "r"(_ph) : "memory");                       \
    if (!_done) {                                                             \
        asm volatile("{\n\t.reg .pred P1;\n\t"                                \
            "WL_%=:\n\t"                                                      \
            "mbarrier.try_wait.parity.acquire.cta.shared::cta.b64 P1, [%0], %1, 0x989680;\n\t" \
            "@P1 bra.uni WD_%=;\n\t"                                          \
            "bra.uni WL_%=;\n\t"                                              \
            "WD_%=:\n\t}"                                                     \
            :: "r"(_mb), "r"(_ph) : "memory");                                \
    }                                                                         \
} while (0)

__device__ __forceinline__ void mma_f16(float* c, const uint32_t* a,
                                        uint32_t b0, uint32_t b1) {
    asm volatile(
        "mma.sync.aligned.m16n8k16.row.col.f32.f16.f16.f32 "
        "{%0,%1,%2,%3}, {%4,%5,%6,%7}, {%8,%9}, {%0,%1,%2,%3};"
        : "+f"(c[0]), "+f"(c[1]), "+f"(c[2]), "+f"(c[3])
        : "r"(a[0]), "r"(a[1]), "r"(a[2]), "r"(a[3]), "r"(b0), "r"(b1));
}

// ---------------------------------------------------------------------------
__global__ void pack_bt_kernel(const float* __restrict__ F,
                               const float* __restrict__ G,
                               __half* __restrict__ Bt) {
    __shared__ float tile[32][33];
    int kb = blockIdx.x * 32;
    int nb = blockIdx.y * 32;
    int tx = threadIdx.x, ty = threadIdx.y;   // block (32, 8)
    #pragma unroll
    for (int r = ty; r < 32; r += 8) {
        int k = kb + r, n = nb + tx;
        float v = (n < 64) ? F[(size_t)k * 64 + n] : G[(size_t)k * 64 + (n - 64)];
        tile[r][tx] = v;
    }
    __syncthreads();
    #pragma unroll
    for (int r = ty; r < 32; r += 8) {
        int n = nb + r, k = kb + tx;
        Bt[(size_t)n * NN + kperm2(k)] = __float2half_rn(tile[tx][r]);
    }
}

// ---------------------------------------------------------------------------
// Layer 1: a16out != null, a16in == null, outT written.
// Layer 2: a16in != null (A from fragments), outR written.
// ---------------------------------------------------------------------------
__global__ void __launch_bounds__(256, 1)
gemm_layer(const float* __restrict__ A, const __half* __restrict__ Bt,
           uint4* __restrict__ a16out, const uint4* __restrict__ a16in,
           __half* __restrict__ outT, float* __restrict__ outR, float scale) {
    extern __shared__ char smem[];
    __shared__ __align__(8) uint64_t mbar[2 * STAGES];

    const int tid  = threadIdx.x;
    const int lane = tid & 31;
    const int w    = tid >> 5;
    const int m0   = blockIdx.x * MT;
    const uint32_t sbase = smem_u32(smem);
    const uint32_t mb    = smem_u32(mbar);
    const int r4 = lane >> 2;
    const int c4 = lane & 3;

    if (tid == 0) {
        #pragma unroll
        for (int s = 0; s < STAGES; s++) {
            MBAR_INIT(mb + 8 * s, 128);                 // full: cp.async x128
            MBAR_INIT(mb + 8 * (STAGES + s), 128);      // empty: 128 consumers
        }
    }
    __syncthreads();

    if (w >= 4) {
        // ================= producers (warps 4-7) =================
        const int t = tid - 128;

        auto issueA = [&](int it) {                     // layer 1: A fp32
            const int k0 = it * KT;
            const uint32_t abase = sbase + (uint32_t)(it & (STAGES - 1)) * STG_B;
            #pragma unroll
            for (int j = 0; j < 4; j++) {               // 512 x 16B
                int ch = t + 128 * j;
                int row = ch >> 3, cc = ch & 7;
                const float* src = A + (size_t)(m0 + row) * NN + k0 + cc * 4;
                CP_ASYNC16(abase + (uint32_t)(row * A_PITCH + cc * 16), src);
            }
        };
        auto issueA16 = [&](int it) {                   // layer 2: A16 frags
            const uint32_t abase = sbase + (uint32_t)(it & (STAGES - 1)) * STG_B;
            const uint4* src = a16in + ((size_t)blockIdx.x * KIT + it) * 256;
            #pragma unroll
            for (int j = 0; j < 2; j++) {               // 256 x 16B
                int ch = t + 128 * j;
                CP_ASYNC16(abase + (uint32_t)(ch * 16), src + ch);
            }
        };
        auto issueB = [&](int it) {
            const int k0 = it * KT;
            const uint32_t bbase = sbase + (uint32_t)(it & (STAGES - 1)) * STG_B
                                   + A_STG_B;
            #pragma unroll
            for (int j = 0; j < 4; j++) {               // 512 x 16B
                int ch = t + 128 * j;
                int col = ch >> 2, q = ch & 3;
                const __half* src = Bt + (size_t)col * NN + k0 + q * 8;
                CP_ASYNC16(bbase + (uint32_t)(col * B_PITCH + q * 16), src);
            }
        };

        if (a16in) {
            for (int it = 0; it < KIT; it++) {
                const int s = it & (STAGES - 1);
                const int r = it >> 3;
                if (r > 0) MBAR_WAIT(mb + 8 * (STAGES + s), (r - 1) & 1);
                issueA16(it);
                issueB(it);
                CP_ASYNC_MBAR_ARRIVE(mb + 8 * s);
            }
        } else {
            for (int it = 0; it < KIT; it++) {
                const int s = it & (STAGES - 1);
                const int r = it >> 3;
                if (r > 0) MBAR_WAIT(mb + 8 * (STAGES + s), (r - 1) & 1);
                issueA(it);
                issueB(it);
                CP_ASYNC_MBAR_ARRIVE(mb + 8 * s);
            }
        }
        return;
    }

    // ================= MMA warps (0-3): 32 rows x 64 cols =================
    const int wm = w >> 1;
    const int wn = w & 1;

    float acc[2][8][4];
    #pragma unroll
    for (int mi = 0; mi < 2; mi++)
        #pragma unroll
        for (int ni = 0; ni < 8; ni++)
            #pragma unroll
            for (int j = 0; j < 4; j++) acc[mi][ni][j] = 0.f;

    const uint32_t aoff = (uint32_t)((wm * 32 + r4) * A_PITCH + 8 * c4);
    const uint32_t boff = (uint32_t)((wn * 64 + r4) * B_PITCH + 16 * c4);

    // full-stage B -> 8 x uint4 (x=h0b0, y=h0b1, z=h1b0, w=h1b1)
    auto loadB = [&](int s, uint4 (&bS)[8]) {
        const char* base = smem + (size_t)s * STG_B + A_STG_B + boff;
        #pragma unroll
        for (int g = 0; g < 8; g++)
            bS[g] = *(const uint4*)(base + g * 8 * B_PITCH);
    };

    if (a16in) {
        // ---------- layer 2: A16 fragment path ----------
        auto loadA16 = [&](int s, uint4 (&U)[4]) {
            const char* base = smem + (size_t)s * STG_B
                               + (uint32_t)(wm * 2048 + lane * 16);
            #pragma unroll
            for (int g = 0; g < 4; g++)
                U[g] = *(const uint4*)(base + g * 512);
        };
        auto mmaH16 = [&](uint4 (&U)[4], uint4 (&bS)[8], int h) {
            #pragma unroll
            for (int mi = 0; mi < 2; mi++) {
                uint32_t af[4];
                if (h) { af[0] = U[2*mi].z; af[1] = U[2*mi+1].z;
                         af[2] = U[2*mi].w; af[3] = U[2*mi+1].w; }
                else   { af[0] = U[2*mi].x; af[1] = U[2*mi+1].x;
                         af[2] = U[2*mi].y; af[3] = U[2*mi+1].y; }
                #pragma unroll
                for (int ni = 0; ni < 8; ni++) {
                    uint32_t b0 = h ? bS[ni].z : bS[ni].x;
                    uint32_t b1 = h ? bS[ni].w : bS[ni].y;
                    mma_f16(acc[mi][ni], af, b0, b1);
                }
            }
        };

        uint4 U[2][4];
        uint4 Bb[2][8];

        MBAR_WAIT(mb + 0, 0);
        loadB(0, Bb[0]);
        loadA16(0, U[0]);

        #pragma unroll 2
        for (int it = 0; it < KIT; it++) {
            const int s = it & (STAGES - 1);
            const int cur = it & 1, nxt = cur ^ 1;

            mmaH16(U[cur], Bb[cur], 0);
            if (it + 1 < KIT) {
                const int s1 = (it + 1) & (STAGES - 1);
                MBAR_WAIT(mb + 8 * s1, ((it + 1) >> 3) & 1);
                loadB(s1, Bb[nxt]);
                loadA16(s1, U[nxt]);
            }
            mmaH16(U[cur], Bb[cur], 1);
            MBAR_ARRIVE(mb + 8 * (STAGES + s));
        }
    } else {
        // ---------- layer 1: fp32 A path + fragment side-write ----------
        auto loadA = [&](int s, int h, uint32_t (&aH)[4][2]) {
            const uint32_t off = (uint32_t)s * STG_B + aoff + (uint32_t)(h * 64);
            #pragma unroll
            for (int g = 0; g < 4; g++) {
                float2 lo = *(const float2*)(smem + off + g * 8 * A_PITCH);
                float2 hi = *(const float2*)(smem + off + g * 8 * A_PITCH + 32);
                aH[g][0] = pack_h2(lo.x * 8192.f, lo.y * 8192.f);
                aH[g][1] = pack_h2(hi.x * 8192.f, hi.y * 8192.f);
            }
        };
        auto mma_half = [&](uint32_t (&aH)[4][2], uint4 (&bS)[8], int h) {
            #pragma unroll
            for (int ni = 0; ni < 8; ni++) {
                uint32_t b0 = h ? bS[ni].z : bS[ni].x;
                uint32_t b1 = h ? bS[ni].w : bS[ni].y;
                {
                    uint32_t af[4] = { aH[0][0], aH[1][0], aH[0][1], aH[1][1] };
                    mma_f16(acc[0][ni], af, b0, b1);
                }
                {
                    uint32_t af[4] = { aH[2][0], aH[3][0], aH[2][1], aH[3][1] };
                    mma_f16(acc[1][ni], af, b0, b1);
                }
            }
        };

        uint32_t A0[4][2], A1[4][2];
        uint4    Bb[2][8];

        MBAR_WAIT(mb + 0, 0);
        loadB(0, Bb[0]);
        loadA(0, 0, A0);

        #pragma unroll 2
        for (int it = 0; it < KIT; it++) {
            const int s = it & (STAGES - 1);
            const int cur = it & 1, nxt = cur ^ 1;

            loadA(s, 1, A1);

            // side-write this stage's fragments (only non-duplicated warps)
            if ((w & 1) == 0) {
                uint4* dst = a16out + ((size_t)blockIdx.x * KIT + it) * 256
                             + (size_t)(wm * 128 + lane);
                #pragma unroll
                for (int g = 0; g < 4; g++)
                    dst[g * 32] = make_uint4(A0[g][0], A0[g][1],
                                             A1[g][0], A1[g][1]);
            }

            mma_half(A0, Bb[cur], 0);
            if (it + 1 < KIT) {
                const int s1 = (it + 1) & (STAGES - 1);
                MBAR_WAIT(mb + 8 * s1, ((it + 1) >> 3) & 1);
                loadB(s1, Bb[nxt]);
                loadA(s1, 0, A0);
            }
            mma_half(A1, Bb[cur], 1);
            MBAR_ARRIVE(mb + 8 * (STAGES + s));
        }
    }

    // ---- epilogue ----
    const int rBase = m0 + wm * 32 + r4;
    const int cBase = wn * 64 + c4 * 2;

    if (outT) {
        // staged transposed store: smem [col][row] (pitch 136B), then each
        // warp streams 32 cols as coalesced 4B lane stores.
        asm volatile("bar.sync 1, 128;" ::: "memory");   // all MMAs done
        #pragma unroll
        for (int mi = 0; mi < 2; mi++) {
            #pragma unroll
            for (int ni = 0; ni < 8; ni++) {
                #pragma unroll
                for (int j = 0; j < 4; j++) {
                    int row_l = wm * 32 + r4 + mi * 16 + (j >> 1) * 8;
                    int col   = cBase + ni * 8 + (j & 1);
                    float v = acc[mi][ni][j] * scale;
                    if (col < 64) v = fmaxf(v, 0.0f);
                    *(__half*)(smem + col * STG_PITCH + row_l * 2) =
                        __float2half_rn(v);
                }
            }
        }
        asm volatile("bar.sync 1, 128;" ::: "memory");
        const int b  = lane >> 4;
        const int jj = lane & 15;
        const int q  = ((jj & 3) << 2) | (jj >> 2);     // kperm2 chunk pos
        #pragma unroll
        for (int c = 0; c < 32; c++) {
            int col = w * 32 + c;
            uint32_t v = *(const uint32_t*)(smem + col * STG_PITCH + lane * 4);
            *(uint32_t*)((char*)outT +
                2 * ((size_t)col * NN + m0 + b * 32 + 2 * q)) = v;
        }
    } else {
        #pragma unroll
        for (int mi = 0; mi < 2; mi++) {
            #pragma unroll
            for (int ni = 0; ni < 8; ni++) {
                #pragma unroll
                for (int jh = 0; jh < 2; jh++) {
                    int row = rBase + mi * 16 + jh * 8;
                    int col = cBase + ni * 8;
                    float v0 = acc[mi][ni][2 * jh]     * scale;
                    float v1 = acc[mi][ni][2 * jh + 1] * scale;
                    if (col < 64) { v0 = fmaxf(v0, 0.f); v1 = fmaxf(v1, 0.f); }
                    *(float2*)(outR + (size_t)row * NB + col) =
                        make_float2(v0, v1);
                }
            }
        }
    }
}

// ---------------------------------------------------------------------------
extern "C" void kernel_launch(void* const* d_in, const int* in_sizes, int n_in,
                              void* d_out, int out_size) {
    (void)in_sizes; (void)n_in; (void)out_size;
    const float* A = (const float*)d_in[0];
    const float* F = (const float*)d_in[1];
    const float* G = (const float*)d_in[2];
    float* out = (float*)d_out;

    __half *bt1 = nullptr, *bt2 = nullptr;
    uint4* a16 = nullptr;
    cudaGetSymbolAddress((void**)&bt1, g_bth1);
    cudaGetSymbolAddress((void**)&bt2, g_bth2);
    cudaGetSymbolAddress((void**)&a16, g_a16);

    cudaFuncSetAttribute(gemm_layer,
                         cudaFuncAttributeMaxDynamicSharedMemorySize, SMEM_BYTES);

    dim3 pb(32, 8), pg(NN / 32, NB / 32);
    pack_bt_kernel<<<pg, pb>>>(F, G, bt1);

    // layer 1: acc = (2^13 A) @ B ; store fp16( acc * 2^-7 ) = 2^6 * (A@B)
    //          + side-write A fragments (fp16 x2^13) to g_a16
    gemm_layer<<<NN / MT, 256, SMEM_BYTES>>>(A, bt1, a16, (const uint4*)nullptr,
                                             bt2, (float*)nullptr, 0.0078125f);
    // layer 2: acc = (2^13 A) @ (2^6 h) ; out = acc * 2^-19  (A from g_a16)
    gemm_layer<<<NN / MT, 256, SMEM_BYTES>>>(A, bt2, (uint4*)nullptr, a16,
                                             (__half*)nullptr, out,
                                             1.0f / 524288.0f);
}

// round 16
// speedup vs baseline: 1.0940x; 1.0940x over previous
#include <cuda_runtime.h>
#include <cuda_fp16.h>
#include <cstdint>

// ---------------------------------------------------------------------------
// out = concat( relu(A@relu(A@F)), A@(A@G) ), A:[8192,8192] f32, F,G:[8192,64]
// Per layer: fused GEMM C[8192,128] = A @ Bt^T, relu on cols [0,64).
// fp16 mma.m16n8k16; 4 producer + 4 consumer warps (R12 chassis).
// R16: STAGES 8->10 (jitter smoothing), A-prefetch depth 6 under PDL.
// ---------------------------------------------------------------------------

#define NN      8192
#define NB      128
#define MT      64              // M rows per CTA -> 128 CTAs
#define KT      32              // K per stage
#define STAGES  10
#define PREF    6               // A-only prefetch depth before GDC_WAIT
#define KIT     (NN / KT)       // 256
#define A_PITCH 160             // bytes per A smem row (fp32 k32 + pad)
#define B_PITCH 64              // bytes per B smem row (fp16 k32)
#define A_STG_B (64 * A_PITCH)  // 10240
#define B_STG_B (128 * B_PITCH) // 8192
#define STG_B   (A_STG_B + B_STG_B)        // 18432
#define SMEM_BYTES (STAGES * STG_B)        // 184320
#define STG_PITCH 136           // staging bytes per col (64 rows fp16 + pad)

__device__ __half g_bth1[NB * NN];   // layer-1 B, fp16 chunk-permuted
__device__ __half g_bth2[NB * NN];   // layer-1 out (x2^6) = layer-2 B

// chunk permutation within each k32 block (2-element chunks):
// chunk j -> position (j%4)*4 + j/4
__device__ __forceinline__ int kperm2(int k) {
    int j = (k >> 1) & 15;
    int p = ((j & 3) << 2) | (j >> 2);
    return (k & ~31) | (p << 1) | (k & 1);
}

__device__ __forceinline__ uint32_t smem_u32(const void* p) {
    uint32_t a;
    asm("{ .reg .u64 t; cvta.to.shared.u64 t, %1; cvt.u32.u64 %0, t; }"
        : "=r"(a) : "l"(p));
    return a;
}

// pack two fp32 -> fp16x2 (lo = first arg)
__device__ __forceinline__ uint32_t pack_h2(float lo, float hi) {
    uint32_t d;
    asm("cvt.rn.f16x2.f32 %0, %1, %2;" : "=r"(d) : "f"(hi), "f"(lo));
    return d;
}

#define GDC_LAUNCH() asm volatile("griddepcontrol.launch_dependents;" ::: "memory")
#define GDC_WAIT()   asm volatile("griddepcontrol.wait;" ::: "memory")

#define CP_ASYNC16(dst, src) \
    asm volatile("cp.async.cg.shared.global [%0], [%1], 16;" \
                 :: "r"(dst), "l"(src) : "memory")

#define MBAR_INIT(addr, cnt) \
    asm volatile("mbarrier.init.shared.b64 [%0], %1;" :: "r"(addr), "r"(cnt) : "memory")
#define MBAR_ARRIVE(addr) \
    asm volatile("mbarrier.arrive.shared.b64 _, [%0];" :: "r"(addr) : "memory")
#define CP_ASYNC_MBAR_ARRIVE(addr) \
    asm volatile("cp.async.mbarrier.arrive.noinc.shared::cta.b64 [%0];" \
                 :: "r"(addr) : "memory")

#define MBAR_WAIT(addr, parity) do {                                          \
    uint32_t _mb = (addr); uint32_t _ph = (parity); uint32_t _done;           \
    asm volatile("{\n\t.reg .pred p;\n\t"                                     \
        "mbarrier.try_wait.parity.acquire.cta.shared::cta.b64 p, [%1], %2;\n\t"\
        "selp.b32 %0, 1, 0, p;\n\t}"                                          \
        : "=r"(_done) : "r"(_mb), "r"(_ph) : "memory");                       \
    if (!_done) {                                                             \
        asm volatile("{\n\t.reg .pred P1;\n\t"                                \
            "WL_%=:\n\t"                                                      \
            "mbarrier.try_wait.parity.acquire.cta.shared::cta.b64 P1, [%0], %1, 0x989680;\n\t" \
            "@P1 bra.uni WD_%=;\n\t"                                          \
            "bra.uni WL_%=;\n\t"                                              \
            "WD_%=:\n\t}"                                                     \
            :: "r"(_mb), "r"(_ph) : "memory");                                \
    }                                                                         \
} while (0)

__device__ __forceinline__ void mma_f16(float* c, const uint32_t* a,
                                        uint32_t b0, uint32_t b1) {
    asm volatile(
        "mma.sync.aligned.m16n8k16.row.col.f32.f16.f16.f32 "
        "{%0,%1,%2,%3}, {%4,%5,%6,%7}, {%8,%9}, {%0,%1,%2,%3};"
        : "+f"(c[0]), "+f"(c[1]), "+f"(c[2]), "+f"(c[3])
        : "r"(a[0]), "r"(a[1]), "r"(a[2]), "r"(a[3]), "r"(b0), "r"(b1));
}

// ---------------------------------------------------------------------------
__global__ void pack_bt_kernel(const float* __restrict__ F,
                               const float* __restrict__ G,
                               __half* __restrict__ Bt) {
    GDC_LAUNCH();                       // let gemm1 launch + prefetch A early
    __shared__ float tile[32][33];
    int kb = blockIdx.x * 32;
    int nb = blockIdx.y * 32;
    int tx = threadIdx.x, ty = threadIdx.y;   // block (32, 8)
    #pragma unroll
    for (int r = ty; r < 32; r += 8) {
        int k = kb + r, n = nb + tx;
        float v = (n < 64) ? F[(size_t)k * 64 + n] : G[(size_t)k * 64 + (n - 64)];
        tile[r][tx] = v;
    }
    __syncthreads();
    #pragma unroll
    for (int r = ty; r < 32; r += 8) {
        int n = nb + r, k = kb + tx;
        Bt[(size_t)n * NN + kperm2(k)] = __float2half_rn(tile[tx][r]);
    }
}

// ---------------------------------------------------------------------------
__global__ void __launch_bounds__(256, 1)
gemm_layer(const float* __restrict__ A, const __half* __restrict__ Bt,
           __half* __restrict__ outT, float* __restrict__ outR, float scale) {
    extern __shared__ char smem[];
    __shared__ __align__(8) uint64_t mbar[2 * STAGES];

    const int tid  = threadIdx.x;
    const int lane = tid & 31;
    const int w    = tid >> 5;
    const int m0   = blockIdx.x * MT;
    const uint32_t sbase = smem_u32(smem);
    const uint32_t mb    = smem_u32(mbar);
    const int r4 = lane >> 2;
    const int c4 = lane & 3;

    if (tid == 0) {
        #pragma unroll
        for (int s = 0; s < STAGES; s++) {
            MBAR_INIT(mb + 8 * s, 128);                 // full: cp.async x128
            MBAR_INIT(mb + 8 * (STAGES + s), 128);      // empty: 128 consumers
        }
    }
    __syncthreads();
    GDC_LAUNCH();          // allow next kernel's CTAs to start as SMs free up

    if (w >= 4) {
        // ================= producers (warps 4-7) =================
        const int t = tid - 128;

        auto issueA = [&](int it, int s) {
            const int k0 = it * KT;
            const uint32_t abase = sbase + (uint32_t)s * STG_B;
            #pragma unroll
            for (int j = 0; j < 4; j++) {               // A: 512 x 16B (fp32)
                int ch = t + 128 * j;
                int row = ch >> 3, cc = ch & 7;
                const float* src = A + (size_t)(m0 + row) * NN + k0 + cc * 4;
                CP_ASYNC16(abase + (uint32_t)(row * A_PITCH + cc * 16), src);
            }
        };
        auto issueB = [&](int it, int s) {
            const int k0 = it * KT;
            const uint32_t bbase = sbase + (uint32_t)s * STG_B + A_STG_B;
            #pragma unroll
            for (int j = 0; j < 4; j++) {               // B: 512 x 16B (fp16)
                int ch = t + 128 * j;
                int col = ch >> 2, q = ch & 3;
                const __half* src = Bt + (size_t)col * NN + k0 + q * 8;
                CP_ASYNC16(bbase + (uint32_t)(col * B_PITCH + q * 16), src);
            }
        };

        // A-only prefetch (no dependency on previous kernel's output)
        #pragma unroll
        for (int it = 0; it < PREF; it++) issueA(it, it);
        GDC_WAIT();                     // previous kernel's Bt now visible
        #pragma unroll
        for (int it = 0; it < PREF; it++) {
            issueB(it, it);
            CP_ASYNC_MBAR_ARRIVE(mb + 8 * it);
        }
        int s = PREF, ws = 0, wph = 0;  // stage slot + empty-wait cursor
        for (int it = PREF; it < KIT; it++) {
            if (it >= STAGES) {
                MBAR_WAIT(mb + 8 * (STAGES + ws), wph);
                if (++ws == STAGES) { ws = 0; wph ^= 1; }
            }
            issueA(it, s);
            issueB(it, s);
            CP_ASYNC_MBAR_ARRIVE(mb + 8 * s);
            if (++s == STAGES) s = 0;
        }
        return;
    }

    // ================= MMA warps (0-3): 32 rows x 64 cols =================
    const int wm = w >> 1;
    const int wn = w & 1;

    float acc[2][8][4];
    #pragma unroll
    for (int mi = 0; mi < 2; mi++)
        #pragma unroll
        for (int ni = 0; ni < 8; ni++)
            #pragma unroll
            for (int j = 0; j < 4; j++) acc[mi][ni][j] = 0.f;

    const uint32_t aoff = (uint32_t)((wm * 32 + r4) * A_PITCH + 8 * c4);
    const uint32_t boff = (uint32_t)((wn * 64 + r4) * B_PITCH + 16 * c4);

    // A half h (k16) of stage slot s -> 8 fp16x2 regs (scaled x2^13)
    auto loadA = [&](int s, int h, uint32_t (&aH)[4][2]) {
        const uint32_t off = (uint32_t)s * STG_B + aoff + (uint32_t)(h * 64);
        #pragma unroll
        for (int g = 0; g < 4; g++) {
            float2 lo = *(const float2*)(smem + off + g * 8 * A_PITCH);
            float2 hi = *(const float2*)(smem + off + g * 8 * A_PITCH + 32);
            aH[g][0] = pack_h2(lo.x * 8192.f, lo.y * 8192.f);
            aH[g][1] = pack_h2(hi.x * 8192.f, hi.y * 8192.f);
        }
    };

    // full-stage B -> 8 x uint4 (x=h0b0, y=h0b1, z=h1b0, w=h1b1)
    auto loadB = [&](int s, uint4 (&bS)[8]) {
        const char* base = smem + (size_t)s * STG_B + A_STG_B + boff;
        #pragma unroll
        for (int g = 0; g < 8; g++)
            bS[g] = *(const uint4*)(base + g * 8 * B_PITCH);
    };

    auto mma_half = [&](uint32_t (&aH)[4][2], uint4 (&bS)[8], int h) {
        #pragma unroll
        for (int ni = 0; ni < 8; ni++) {
            uint32_t b0 = h ? bS[ni].z : bS[ni].x;
            uint32_t b1 = h ? bS[ni].w : bS[ni].y;
            {
                uint32_t af[4] = { aH[0][0], aH[1][0], aH[0][1], aH[1][1] };
                mma_f16(acc[0][ni], af, b0, b1);
            }
            {
                uint32_t af[4] = { aH[2][0], aH[3][0], aH[2][1], aH[3][1] };
                mma_f16(acc[1][ni], af, b0, b1);
            }
        }
    };

    uint32_t A0[4][2], A1[4][2];
    uint4    Bb[2][8];

    MBAR_WAIT(mb + 0, 0);
    loadB(0, Bb[0]);
    loadA(0, 0, A0);

    int s = 0;                 // slot of current it
    int ns = 1, wph = 0;       // slot + phase of next full-wait (it+1)

    #pragma unroll 2
    for (int it = 0; it < KIT; it++) {
        const int cur = it & 1, nxt = cur ^ 1;

        loadA(s, 1, A1);
        mma_half(A0, Bb[cur], 0);

        if (it + 1 < KIT) {
            MBAR_WAIT(mb + 8 * ns, wph);
            loadB(ns, Bb[nxt]);
            loadA(ns, 0, A0);
        }
        mma_half(A1, Bb[cur], 1);

        MBAR_ARRIVE(mb + 8 * (STAGES + s));

        s = ns;
        if (++ns == STAGES) { ns = 0; wph ^= 1; }
    }

    // ---- epilogue ----
    const int rBase = m0 + wm * 32 + r4;
    const int cBase = wn * 64 + c4 * 2;

    if (outT) {
        // staged transposed store: smem [col][row] (pitch 136B), then each
        // warp streams 32 cols as coalesced 4B lane stores.
        asm volatile("bar.sync 1, 128;" ::: "memory");   // all MMAs done
        #pragma unroll
        for (int mi = 0; mi < 2; mi++) {
            #pragma unroll
            for (int ni = 0; ni < 8; ni++) {
                #pragma unroll
                for (int j = 0; j < 4; j++) {
                    int row_l = wm * 32 + r4 + mi * 16 + (j >> 1) * 8;
                    int col   = cBase + ni * 8 + (j & 1);
                    float v = acc[mi][ni][j] * scale;
                    if (col < 64) v = fmaxf(v, 0.0f);
                    *(__half*)(smem + col * STG_PITCH + row_l * 2) =
                        __float2half_rn(v);
                }
            }
        }
        asm volatile("bar.sync 1, 128;" ::: "memory");
        const int b  = lane >> 4;
        const int jj = lane & 15;
        const int q  = ((jj & 3) << 2) | (jj >> 2);     // kperm2 chunk pos
        #pragma unroll
        for (int c = 0; c < 32; c++) {
            int col = w * 32 + c;
            uint32_t v = *(const uint32_t*)(smem + col * STG_PITCH + lane * 4);
            *(uint32_t*)((char*)outT +
                2 * ((size_t)col * NN + m0 + b * 32 + 2 * q)) = v;
        }
    } else {
        #pragma unroll
        for (int mi = 0; mi < 2; mi++) {
            #pragma unroll
            for (int ni = 0; ni < 8; ni++) {
                #pragma unroll
                for (int jh = 0; jh < 2; jh++) {
                    int row = rBase + mi * 16 + jh * 8;
                    int col = cBase + ni * 8;
                    float v0 = acc[mi][ni][2 * jh]     * scale;
                    float v1 = acc[mi][ni][2 * jh + 1] * scale;
                    if (col < 64) { v0 = fmaxf(v0, 0.f); v1 = fmaxf(v1, 0.f); }
                    *(float2*)(outR + (size_t)row * NB + col) =
                        make_float2(v0, v1);
                }
            }
        }
    }
}

// ---------------------------------------------------------------------------
extern "C" void kernel_launch(void* const* d_in, const int* in_sizes, int n_in,
                              void* d_out, int out_size) {
    (void)in_sizes; (void)n_in; (void)out_size;
    const float* A = (const float*)d_in[0];
    const float* F = (const float*)d_in[1];
    const float* G = (const float*)d_in[2];
    float* out = (float*)d_out;

    __half *bt1 = nullptr, *bt2 = nullptr;
    cudaGetSymbolAddress((void**)&bt1, g_bth1);
    cudaGetSymbolAddress((void**)&bt2, g_bth2);

    cudaFuncSetAttribute(gemm_layer,
                         cudaFuncAttributeMaxDynamicSharedMemorySize, SMEM_BYTES);

    dim3 pb(32, 8), pg(NN / 32, NB / 32);
    pack_bt_kernel<<<pg, pb>>>(F, G, bt1);

    cudaLaunchAttribute at[1];
    at[0].id = cudaLaunchAttributeProgrammaticStreamSerialization;
    at[0].val.programmaticStreamSerializationAllowed = 1;

    cudaLaunchConfig_t cfg = {};
    cfg.gridDim = dim3(NN / MT);
    cfg.blockDim = dim3(256);
    cfg.dynamicSmemBytes = SMEM_BYTES;
    cfg.stream = 0;
    cfg.attrs = at;
    cfg.numAttrs = 1;

    // layer 1: acc = (2^13 A) @ B ; store fp16( acc * 2^-7 ) = 2^6 * (A@B)
    cudaError_t e1 = cudaLaunchKernelEx(&cfg, gemm_layer,
                                        A, (const __half*)bt1, bt2,
                                        (float*)nullptr, 0.0078125f);
    if (e1 != cudaSuccess)
        gemm_layer<<<NN / MT, 256, SMEM_BYTES>>>(A, bt1, bt2, nullptr,
                                                 0.0078125f);

    // layer 2: acc = (2^13 A) @ (2^6 h) ; out = acc * 2^-19
    cudaError_t e2 = cudaLaunchKernelEx(&cfg, gemm_layer,
                                        A, (const __half*)bt2, (__half*)nullptr,
                                        out, 1.0f / 524288.0f);
    if (e2 != cudaSuccess)
        gemm_layer<<<NN / MT, 256, SMEM_BYTES>>>(A, bt2, nullptr, out,
                                                 1.0f / 524288.0f);
}

// round 17
// speedup vs baseline: 1.1917x; 1.0893x over previous
#include <cuda_runtime.h>
#include <cuda_fp16.h>
#include <cstdint>

// ---------------------------------------------------------------------------
// out = concat( relu(A@relu(A@F)), A@(A@G) ), A:[8192,8192] f32, F,G:[8192,64]
// Per layer: fused GEMM C[8192,128] = A @ Bt^T, relu on cols [0,64).
// fp16 mma.m16n8k16; 4 producer + 4 consumer warps (R12 chassis).
// R17: PDL made hazard-free (launch_dependents AFTER producing stores),
// A-prefetch depth 6. Everything else byte-identical to R12 (154.9us best).
// ---------------------------------------------------------------------------

#define NN      8192
#define NB      128
#define MT      64              // M rows per CTA -> 128 CTAs
#define KT      32              // K per stage
#define STAGES  8
#define PREF    6               // A-only prefetch depth before GDC_WAIT
#define KIT     (NN / KT)       // 256
#define A_PITCH 160             // bytes per A smem row (fp32 k32 + pad)
#define B_PITCH 64              // bytes per B smem row (fp16 k32)
#define A_STG_B (64 * A_PITCH)  // 10240
#define B_STG_B (128 * B_PITCH) // 8192
#define STG_B   (A_STG_B + B_STG_B)        // 18432
#define SMEM_BYTES (STAGES * STG_B)        // 147456
#define STG_PITCH 136           // staging bytes per col (64 rows fp16 + pad)

__device__ __half g_bth1[NB * NN];   // layer-1 B, fp16 chunk-permuted
__device__ __half g_bth2[NB * NN];   // layer-1 out (x2^6) = layer-2 B

// chunk permutation within each k32 block (2-element chunks):
// chunk j -> position (j%4)*4 + j/4
__device__ __forceinline__ int kperm2(int k) {
    int j = (k >> 1) & 15;
    int p = ((j & 3) << 2) | (j >> 2);
    return (k & ~31) | (p << 1) | (k & 1);
}

__device__ __forceinline__ uint32_t smem_u32(const void* p) {
    uint32_t a;
    asm("{ .reg .u64 t; cvta.to.shared.u64 t, %1; cvt.u32.u64 %0, t; }"
        : "=r"(a) : "l"(p));
    return a;
}

// pack two fp32 -> fp16x2 (lo = first arg)
__device__ __forceinline__ uint32_t pack_h2(float lo, float hi) {
    uint32_t d;
    asm("cvt.rn.f16x2.f32 %0, %1, %2;" : "=r"(d) : "f"(hi), "f"(lo));
    return d;
}

#define GDC_LAUNCH() asm volatile("griddepcontrol.launch_dependents;" ::: "memory")
#define GDC_WAIT()   asm volatile("griddepcontrol.wait;" ::: "memory")

#define CP_ASYNC16(dst, src) \
    asm volatile("cp.async.cg.shared.global [%0], [%1], 16;" \
                 :: "r"(dst), "l"(src) : "memory")

#define MBAR_INIT(addr, cnt) \
    asm volatile("mbarrier.init.shared.b64 [%0], %1;" :: "r"(addr), "r"(cnt) : "memory")
#define MBAR_ARRIVE(addr) \
    asm volatile("mbarrier.arrive.shared.b64 _, [%0];" :: "r"(addr) : "memory")
#define CP_ASYNC_MBAR_ARRIVE(addr) \
    asm volatile("cp.async.mbarrier.arrive.noinc.shared::cta.b64 [%0];" \
                 :: "r"(addr) : "memory")

#define MBAR_WAIT(addr, parity) do {                                          \
    uint32_t _mb = (addr); uint32_t _ph = (parity); uint32_t _done;           \
    asm volatile("{\n\t.reg .pred p;\n\t"                                     \
        "mbarrier.try_wait.parity.acquire.cta.shared::cta.b64 p, [%1], %2;\n\t"\
        "selp.b32 %0, 1, 0, p;\n\t}"                                          \
        : "=r"(_done) : "r"(_mb), "r"(_ph) : "memory");                       \
    if (!_done) {                                                             \
        asm volatile("{\n\t.reg .pred P1;\n\t"                                \
            "WL_%=:\n\t"                                                      \
            "mbarrier.try_wait.parity.acquire.cta.shared::cta.b64 P1, [%0], %1, 0x989680;\n\t" \
            "@P1 bra.uni WD_%=;\n\t"                                          \
            "bra.uni WL_%=;\n\t"                                              \
            "WD_%=:\n\t}"                                                     \
            :: "r"(_mb), "r"(_ph) : "memory");                                \
    }                                                                         \
} while (0)

__device__ __forceinline__ void mma_f16(float* c, const uint32_t* a,
                                        uint32_t b0, uint32_t b1) {
    asm volatile(
        "mma.sync.aligned.m16n8k16.row.col.f32.f16.f16.f32 "
        "{%0,%1,%2,%3}, {%4,%5,%6,%7}, {%8,%9}, {%0,%1,%2,%3};"
        : "+f"(c[0]), "+f"(c[1]), "+f"(c[2]), "+f"(c[3])
        : "r"(a[0]), "r"(a[1]), "r"(a[2]), "r"(a[3]), "r"(b0), "r"(b1));
}

// ---------------------------------------------------------------------------
__global__ void pack_bt_kernel(const float* __restrict__ F,
                               const float* __restrict__ G,
                               __half* __restrict__ Bt) {
    __shared__ float tile[32][33];
    int kb = blockIdx.x * 32;
    int nb = blockIdx.y * 32;
    int tx = threadIdx.x, ty = threadIdx.y;   // block (32, 8)
    #pragma unroll
    for (int r = ty; r < 32; r += 8) {
        int k = kb + r, n = nb + tx;
        float v = (n < 64) ? F[(size_t)k * 64 + n] : G[(size_t)k * 64 + (n - 64)];
        tile[r][tx] = v;
    }
    __syncthreads();
    #pragma unroll
    for (int r = ty; r < 32; r += 8) {
        int n = nb + r, k = kb + tx;
        Bt[(size_t)n * NN + kperm2(k)] = __float2half_rn(tile[tx][r]);
    }
    GDC_LAUNCH();        // AFTER stores: dependents may start, data visible
}

// ---------------------------------------------------------------------------
__global__ void __launch_bounds__(256, 1)
gemm_layer(const float* __restrict__ A, const __half* __restrict__ Bt,
           __half* __restrict__ outT, float* __restrict__ outR, float scale) {
    extern __shared__ char smem[];
    __shared__ __align__(8) uint64_t mbar[2 * STAGES];

    const int tid  = threadIdx.x;
    const int lane = tid & 31;
    const int w    = tid >> 5;
    const int m0   = blockIdx.x * MT;
    const uint32_t sbase = smem_u32(smem);
    const uint32_t mb    = smem_u32(mbar);
    const int r4 = lane >> 2;
    const int c4 = lane & 3;

    if (tid == 0) {
        #pragma unroll
        for (int s = 0; s < STAGES; s++) {
            MBAR_INIT(mb + 8 * s, 128);                 // full
            MBAR_INIT(mb + 8 * (STAGES + s), 128);      // empty
        }
    }
    __syncthreads();

    if (w >= 4) {
        // ================= producers (warps 4-7) =================
        const int t = tid - 128;

        auto issueA = [&](int it) {
            const int k0 = it * KT;
            const uint32_t abase = sbase + (uint32_t)(it & (STAGES - 1)) * STG_B;
            #pragma unroll
            for (int j = 0; j < 4; j++) {               // A: 512 x 16B (fp32)
                int ch = t + 128 * j;
                int row = ch >> 3, cc = ch & 7;
                const float* src = A + (size_t)(m0 + row) * NN + k0 + cc * 4;
                CP_ASYNC16(abase + (uint32_t)(row * A_PITCH + cc * 16), src);
            }
        };
        auto issueB = [&](int it) {
            const int k0 = it * KT;
            const uint32_t bbase = sbase + (uint32_t)(it & (STAGES - 1)) * STG_B
                                   + A_STG_B;
            #pragma unroll
            for (int j = 0; j < 4; j++) {               // B: 512 x 16B (fp16)
                int ch = t + 128 * j;
                int col = ch >> 2, q = ch & 3;
                const __half* src = Bt + (size_t)col * NN + k0 + q * 8;
                CP_ASYNC16(bbase + (uint32_t)(col * B_PITCH + q * 16), src);
            }
        };

        // A-only prefetch (no dependency on previous kernel's output)
        #pragma unroll
        for (int it = 0; it < PREF; it++) issueA(it);
        GDC_WAIT();                     // previous kernel's Bt now visible
        #pragma unroll
        for (int it = 0; it < PREF; it++) {
            issueB(it);
            CP_ASYNC_MBAR_ARRIVE(mb + 8 * it);
        }
        for (int it = PREF; it < KIT; it++) {
            const int s = it & (STAGES - 1);
            const int r = it >> 3;
            if (r > 0) MBAR_WAIT(mb + 8 * (STAGES + s), (r - 1) & 1);
            issueA(it);
            issueB(it);
            CP_ASYNC_MBAR_ARRIVE(mb + 8 * s);
        }
        return;                          // producers do not signal PDL
    }

    // ================= MMA warps (0-3): 32 rows x 64 cols =================
    const int wm = w >> 1;
    const int wn = w & 1;

    float acc[2][8][4];
    #pragma unroll
    for (int mi = 0; mi < 2; mi++)
        #pragma unroll
        for (int ni = 0; ni < 8; ni++)
            #pragma unroll
            for (int j = 0; j < 4; j++) acc[mi][ni][j] = 0.f;

    const uint32_t aoff = (uint32_t)((wm * 32 + r4) * A_PITCH + 8 * c4);
    const uint32_t boff = (uint32_t)((wn * 64 + r4) * B_PITCH + 16 * c4);

    // A half h (k16) of stage s -> 8 fp16x2 regs (scaled x2^13)
    auto loadA = [&](int s, int h, uint32_t (&aH)[4][2]) {
        const uint32_t off = (uint32_t)s * STG_B + aoff + (uint32_t)(h * 64);
        #pragma unroll
        for (int g = 0; g < 4; g++) {
            float2 lo = *(const float2*)(smem + off + g * 8 * A_PITCH);
            float2 hi = *(const float2*)(smem + off + g * 8 * A_PITCH + 32);
            aH[g][0] = pack_h2(lo.x * 8192.f, lo.y * 8192.f);
            aH[g][1] = pack_h2(hi.x * 8192.f, hi.y * 8192.f);
        }
    };

    // full-stage B -> 8 x uint4 (x=h0b0, y=h0b1, z=h1b0, w=h1b1)
    auto loadB = [&](int s, uint4 (&bS)[8]) {
        const char* base = smem + (size_t)s * STG_B + A_STG_B + boff;
        #pragma unroll
        for (int g = 0; g < 8; g++)
            bS[g] = *(const uint4*)(base + g * 8 * B_PITCH);
    };

    auto mma_half = [&](uint32_t (&aH)[4][2], uint4 (&bS)[8], int h) {
        #pragma unroll
        for (int ni = 0; ni < 8; ni++) {
            uint32_t b0 = h ? bS[ni].z : bS[ni].x;
            uint32_t b1 = h ? bS[ni].w : bS[ni].y;
            {
                uint32_t af[4] = { aH[0][0], aH[1][0], aH[0][1], aH[1][1] };
                mma_f16(acc[0][ni], af, b0, b1);
            }
            {
                uint32_t af[4] = { aH[2][0], aH[3][0], aH[2][1], aH[3][1] };
                mma_f16(acc[1][ni], af, b0, b1);
            }
        }
    };

    uint32_t A0[4][2], A1[4][2];
    uint4    Bb[2][8];

    MBAR_WAIT(mb + 0, 0);
    loadB(0, Bb[0]);
    loadA(0, 0, A0);

    #pragma unroll 2
    for (int it = 0; it < KIT; it++) {
        const int s = it & (STAGES - 1);
        const int cur = it & 1, nxt = cur ^ 1;

        loadA(s, 1, A1);
        mma_half(A0, Bb[cur], 0);

        if (it + 1 < KIT) {
            const int s1 = (it + 1) & (STAGES - 1);
            MBAR_WAIT(mb + 8 * s1, ((it + 1) >> 3) & 1);
            loadB(s1, Bb[nxt]);
            loadA(s1, 0, A0);
        }
        mma_half(A1, Bb[cur], 1);

        MBAR_ARRIVE(mb + 8 * (STAGES + s));
    }

    // ---- epilogue ----
    const int rBase = m0 + wm * 32 + r4;
    const int cBase = wn * 64 + c4 * 2;

    if (outT) {
        // staged transposed store: smem [col][row] (pitch 136B), then each
        // warp streams 32 cols as coalesced 4B lane stores.
        asm volatile("bar.sync 1, 128;" ::: "memory");   // all MMAs done
        #pragma unroll
        for (int mi = 0; mi < 2; mi++) {
            #pragma unroll
            for (int ni = 0; ni < 8; ni++) {
                #pragma unroll
                for (int j = 0; j < 4; j++) {
                    int row_l = wm * 32 + r4 + mi * 16 + (j >> 1) * 8;
                    int col   = cBase + ni * 8 + (j & 1);
                    float v = acc[mi][ni][j] * scale;
                    if (col < 64) v = fmaxf(v, 0.0f);
                    *(__half*)(smem + col * STG_PITCH + row_l * 2) =
                        __float2half_rn(v);
                }
            }
        }
        asm volatile("bar.sync 1, 128;" ::: "memory");
        const int b  = lane >> 4;
        const int jj = lane & 15;
        const int q  = ((jj & 3) << 2) | (jj >> 2);     // kperm2 chunk pos
        #pragma unroll
        for (int c = 0; c < 32; c++) {
            int col = w * 32 + c;
            uint32_t v = *(const uint32_t*)(smem + col * STG_PITCH + lane * 4);
            *(uint32_t*)((char*)outT +
                2 * ((size_t)col * NN + m0 + b * 32 + 2 * q)) = v;
        }
    } else {
        #pragma unroll
        for (int mi = 0; mi < 2; mi++) {
            #pragma unroll
            for (int ni = 0; ni < 8; ni++) {
                #pragma unroll
                for (int jh = 0; jh < 2; jh++) {
                    int row = rBase + mi * 16 + jh * 8;
                    int col = cBase + ni * 8;
                    float v0 = acc[mi][ni][2 * jh]     * scale;
                    float v1 = acc[mi][ni][2 * jh + 1] * scale;
                    if (col < 64) { v0 = fmaxf(v0, 0.f); v1 = fmaxf(v1, 0.f); }
                    *(float2*)(outR + (size_t)row * NB + col) =
                        make_float2(v0, v1);
                }
            }
        }
    }

    GDC_LAUNCH();        // AFTER epilogue stores: safe PDL hand-off
}

// ---------------------------------------------------------------------------
extern "C" void kernel_launch(void* const* d_in, const int* in_sizes, int n_in,
                              void* d_out, int out_size) {
    (void)in_sizes; (void)n_in; (void)out_size;
    const float* A = (const float*)d_in[0];
    const float* F = (const float*)d_in[1];
    const float* G = (const float*)d_in[2];
    float* out = (float*)d_out;

    __half *bt1 = nullptr, *bt2 = nullptr;
    cudaGetSymbolAddress((void**)&bt1, g_bth1);
    cudaGetSymbolAddress((void**)&bt2, g_bth2);

    cudaFuncSetAttribute(gemm_layer,
                         cudaFuncAttributeMaxDynamicSharedMemorySize, SMEM_BYTES);

    dim3 pb(32, 8), pg(NN / 32, NB / 32);
    pack_bt_kernel<<<pg, pb>>>(F, G, bt1);

    cudaLaunchAttribute at[1];
    at[0].id = cudaLaunchAttributeProgrammaticStreamSerialization;
    at[0].val.programmaticStreamSerializationAllowed = 1;

    cudaLaunchConfig_t cfg = {};
    cfg.gridDim = dim3(NN / MT);
    cfg.blockDim = dim3(256);
    cfg.dynamicSmemBytes = SMEM_BYTES;
    cfg.stream = 0;
    cfg.attrs = at;
    cfg.numAttrs = 1;

    // layer 1: acc = (2^13 A) @ B ; store fp16( acc * 2^-7 ) = 2^6 * (A@B)
    cudaError_t e1 = cudaLaunchKernelEx(&cfg, gemm_layer,
                                        A, (const __half*)bt1, bt2,
                                        (float*)nullptr, 0.0078125f);
    if (e1 != cudaSuccess)
        gemm_layer<<<NN / MT, 256, SMEM_BYTES>>>(A, bt1, bt2, nullptr,
                                                 0.0078125f);

    // layer 2: acc = (2^13 A) @ (2^6 h) ; out = acc * 2^-19
    cudaError_t e2 = cudaLaunchKernelEx(&cfg, gemm_layer,
                                        A, (const __half*)bt2, (__half*)nullptr,
                                        out, 1.0f / 524288.0f);
    if (e2 != cudaSuccess)
        gemm_layer<<<NN / MT, 256, SMEM_BYTES>>>(A, bt2, nullptr, out,
                                                 1.0f / 524288.0f);
}